// round 5
// baseline (speedup 1.0000x reference)
#include <cuda_runtime.h>
#include <cstdint>

#define RANK  200
#define NNZ   500000
#define N_ENT 200000
#define N_REL 500
#define RV4   (RANK / 4)   // 50 float4 per row

#define TILE   4096        // nnz per scatter block
#define ITEMS  16          // TILE / 256

// Scratch (__device__ globals: zero-initialized at module load; every array is
// fully rebuilt or explicitly self-reset each invocation, so the correctness
// run and every graph replay start from identical state).
__device__ float g_deriv[NNZ];     // 2 * (kruskal - val) per nnz
__device__ int   g_win_a[N_ENT];   // winner key: n+1 (subj) or n+1+NNZ (obj); 0 = none (pass_b self-resets)
__device__ int   g_win_b[N_REL];   // winner key: n+1; 0 = none (pass_b self-resets)
__device__ int   g_hist[N_REL];    // relation histogram (scan kernel resets to 0 after use)
__device__ int   g_off[N_REL];     // bucket cursors (rebuilt by scan each invocation)
__device__ int4  g_sorted[NNZ];    // (s, r, o, n) sorted by relation (fully rewritten)

// ---------------------------------------------------------------------------
// Sort stage 1: smem-aggregated relation histogram.
// ---------------------------------------------------------------------------
__global__ void __launch_bounds__(256) hist_kernel(const int* __restrict__ coo) {
    __shared__ int sh[N_REL];
    for (int i = threadIdx.x; i < N_REL; i += blockDim.x) sh[i] = 0;
    __syncthreads();
    int stride = gridDim.x * blockDim.x;
    for (int n = blockIdx.x * blockDim.x + threadIdx.x; n < NNZ; n += stride)
        atomicAdd(&sh[__ldg(coo + 3 * n + 1)], 1);
    __syncthreads();
    for (int i = threadIdx.x; i < N_REL; i += blockDim.x)
        if (sh[i]) atomicAdd(&g_hist[i], sh[i]);
}

// ---------------------------------------------------------------------------
// Sort stage 2: exclusive scan of 500 bucket counts (single block), then
// self-reset g_hist to 0 for the next invocation.
// ---------------------------------------------------------------------------
__global__ void scan_kernel() {
    __shared__ int sh[512];
    int i = threadIdx.x;
    sh[i] = (i < N_REL) ? g_hist[i] : 0;
    __syncthreads();
    for (int d = 1; d < 512; d <<= 1) {
        int v = (i >= d) ? sh[i - d] : 0;
        __syncthreads();
        sh[i] += v;
        __syncthreads();
    }
    if (i < N_REL) {
        g_off[i]  = (i == 0) ? 0 : sh[i - 1];
        g_hist[i] = 0;                       // self-reset for next invocation
    }
}

// ---------------------------------------------------------------------------
// Sort stage 3: BLOCK-AGGREGATED scatter (the R3 version's 500K contended
// global atomics were the failure; here it's ~123 blocks x <=500 reservation
// atomics). Each block ranks its TILE items in smem, reserves one global
// range per non-empty bucket, then writes (s,r,o,n) tuples.
// ---------------------------------------------------------------------------
__global__ void __launch_bounds__(256) scatter_kernel(const int* __restrict__ coo) {
    __shared__ int sh_cnt[N_REL];
    __shared__ int sh_base[N_REL];

    for (int i = threadIdx.x; i < N_REL; i += blockDim.x) sh_cnt[i] = 0;
    __syncthreads();

    int base_n = blockIdx.x * TILE;
    int rr[ITEMS], lr[ITEMS];

    #pragma unroll
    for (int it = 0; it < ITEMS; it++) {
        int n = base_n + threadIdx.x + it * 256;
        if (n < NNZ) {
            int r = __ldg(coo + 3 * n + 1);
            rr[it] = r;
            lr[it] = atomicAdd(&sh_cnt[r], 1);   // local rank within (block, bucket)
        }
    }
    __syncthreads();

    for (int r = threadIdx.x; r < N_REL; r += blockDim.x) {
        int c = sh_cnt[r];
        sh_base[r] = c ? atomicAdd(&g_off[r], c) : 0;  // one global atomic per bucket
    }
    __syncthreads();

    #pragma unroll
    for (int it = 0; it < ITEMS; it++) {
        int n = base_n + threadIdx.x + it * 256;
        if (n < NNZ) {
            int s = __ldg(coo + 3 * n + 0);
            int o = __ldg(coo + 3 * n + 2);
            g_sorted[sh_base[rr[it]] + lr[it]] = make_int4(s, rr[it], o, n);
        }
    }
}

// ---------------------------------------------------------------------------
// Pass A: one warp per SORTED nnz. Consecutive warps share the same b row ->
// b gathers become L1 hits and drop out of LTS traffic. a gathers use L2-only
// loads so they don't evict b from L1. Winners raced with atomicMax on the
// ORIGINAL index n, reproducing XLA scatter-overwrite semantics (obj class
// beats subj class; within a class, higher n wins).
// ---------------------------------------------------------------------------
__global__ void __launch_bounds__(256) pass_a_kernel(
    const float* __restrict__ vals,
    const float* __restrict__ a,
    const float* __restrict__ b,
    float*       __restrict__ loss)
{
    int warp = (blockIdx.x * blockDim.x + threadIdx.x) >> 5;
    int lane = threadIdx.x & 31;
    if (warp >= NNZ) return;

    int4 t = g_sorted[warp];   // same address across the warp -> broadcast
    int s = t.x, r = t.y, o = t.z, n = t.w;

    const float4* a0 = (const float4*)(a + (size_t)s * RANK);
    const float4* b1 = (const float4*)(b + (size_t)r * RANK);
    const float4* a2 = (const float4*)(a + (size_t)o * RANK);

    float sum = 0.0f;
    #pragma unroll
    for (int it = 0; it < 2; it++) {
        int j = lane + it * 32;
        if (j < RV4) {
            float4 x = __ldcg(a0 + j);   // a: L2-only (no L1 reuse; keep L1 for b)
            float4 z = __ldcg(a2 + j);
            float4 y = __ldg (b1 + j);   // b: L1-cached, shared across warps
            sum += x.x * y.x * z.x;
            sum += x.y * y.y * z.y;
            sum += x.z * y.z * z.z;
            sum += x.w * y.w * z.w;
        }
    }
    #pragma unroll
    for (int off = 16; off; off >>= 1)
        sum += __shfl_down_sync(0xffffffffu, sum, off);

    if (lane == 0) {
        float diff = sum - __ldg(vals + n);
        __stcs(loss + n, diff * diff);          // streaming: never re-read
        g_deriv[n] = 2.0f * diff;
        atomicMax(&g_win_a[s], n + 1);          // subj class
        atomicMax(&g_win_a[o], n + 1 + NNZ);    // obj class (beats subj)
        atomicMax(&g_win_b[r], n + 1);
    }
}

// ---------------------------------------------------------------------------
// Pass B (fused): warps [0, N_ENT) -> grad_a rows, warps [N_ENT, N_ENT+N_REL)
// -> grad_b rows. Loser rows get zeros (doubles as output init). Winner rows
// re-gather the two needed embedding rows and write d * x * y with streaming
// stores. Each warp resets its winner slot to 0 for the next invocation.
// ---------------------------------------------------------------------------
__global__ void __launch_bounds__(256) pass_b_kernel(
    const int*   __restrict__ coo,
    const float* __restrict__ a,
    const float* __restrict__ b,
    float*       __restrict__ grad_a,
    float*       __restrict__ grad_b)
{
    int warp = (blockIdx.x * blockDim.x + threadIdx.x) >> 5;
    int lane = threadIdx.x & 31;
    if (warp >= N_ENT + N_REL) return;

    float4* out;
    const float4* x;
    const float4* y;
    float d = 0.0f;
    bool have = false;

    if (warp < N_ENT) {
        out = (float4*)(grad_a + (size_t)warp * RANK);
        int k = g_win_a[warp];
        if (k > 0) {
            if (lane == 0) g_win_a[warp] = 0;        // self-reset
            bool is_obj = (k > NNZ);
            int  n      = is_obj ? (k - 1 - NNZ) : (k - 1);
            int s = coo[3 * n + 0];
            int r = coo[3 * n + 1];
            int o = coo[3 * n + 2];
            d = g_deriv[n];
            if (is_obj) {        // g_c = d * a0 * b1
                x = (const float4*)(a + (size_t)s * RANK);
                y = (const float4*)(b + (size_t)r * RANK);
            } else {             // g_a = d * b1 * a2
                x = (const float4*)(b + (size_t)r * RANK);
                y = (const float4*)(a + (size_t)o * RANK);
            }
            have = true;
        }
    } else {
        int row = warp - N_ENT;
        out = (float4*)(grad_b + (size_t)row * RANK);
        int k = g_win_b[row];
        if (k > 0) {
            if (lane == 0) g_win_b[row] = 0;         // self-reset
            int n = k - 1;
            int s = coo[3 * n + 0];
            int o = coo[3 * n + 2];
            d = g_deriv[n];
            x = (const float4*)(a + (size_t)s * RANK);   // g_b = d * a0 * a2
            y = (const float4*)(a + (size_t)o * RANK);
            have = true;
        }
    }

    if (!have) {
        float4 z = make_float4(0.f, 0.f, 0.f, 0.f);
        #pragma unroll
        for (int it = 0; it < 2; it++) {
            int j = lane + it * 32;
            if (j < RV4) __stcs(out + j, z);
        }
        return;
    }

    #pragma unroll
    for (int it = 0; it < 2; it++) {
        int j = lane + it * 32;
        if (j < RV4) {
            float4 u = __ldcg(x + j);
            float4 v = __ldcg(y + j);
            float4 w = make_float4(d * u.x * v.x, d * u.y * v.y,
                                   d * u.z * v.z, d * u.w * v.w);
            __stcs(out + j, w);
        }
    }
}

// ---------------------------------------------------------------------------
// Launch. Inputs (metadata order): coo_ns int32 [NNZ,3], vals_ns f32 [NNZ],
// a f32 [N_ENT,RANK], b f32 [N_REL,RANK].
// Output: loss[NNZ] | grad_a[N_ENT*RANK] | grad_b[N_REL*RANK]  (f32).
// ---------------------------------------------------------------------------
extern "C" void kernel_launch(void* const* d_in, const int* in_sizes, int n_in,
                              void* d_out, int out_size)
{
    const int*   coo  = (const int*)d_in[0];
    const float* vals = (const float*)d_in[1];
    const float* a    = (const float*)d_in[2];
    const float* b    = (const float*)d_in[3];

    float* out    = (float*)d_out;
    float* loss   = out;
    float* grad_a = out + NNZ;
    float* grad_b = out + NNZ + (size_t)N_ENT * RANK;

    hist_kernel<<<296, 256>>>(coo);
    scan_kernel<<<1, 512>>>();
    scatter_kernel<<<(NNZ + TILE - 1) / TILE, 256>>>(coo);

    {   // one warp per sorted nnz
        long long threads = (long long)NNZ * 32;
        int blocks = (int)((threads + 255) / 256);
        pass_a_kernel<<<blocks, 256>>>(vals, a, b, loss);
    }
    {   // one warp per output row (entity rows then relation rows)
        long long threads = (long long)(N_ENT + N_REL) * 32;
        int blocks = (int)((threads + 255) / 256);
        pass_b_kernel<<<blocks, 256>>>(coo, a, b, grad_a, grad_b);
    }
}

// round 6
// speedup vs baseline: 1.8679x; 1.8679x over previous
#include <cuda_runtime.h>
#include <cstdint>

#define RANK  200
#define NNZ   500000
#define N_ENT 200000
#define N_REL 500
#define RV4   (RANK / 4)   // 50 float4 per row

#define TILE   4096        // nnz per scatter block
#define ITEMS  16          // TILE / 256

// Scratch (__device__ globals: zero-initialized at module load; every array is
// fully rebuilt or explicitly self-reset each invocation, so the correctness
// run and every graph replay start from identical state).
__device__ float g_deriv[NNZ];     // 2 * (kruskal - val) per nnz
__device__ int   g_win_a[N_ENT];   // winner key: n+1 (subj) or n+1+NNZ (obj); 0 = none (pass_b self-resets)
__device__ int   g_win_b[N_REL];   // winner key: n+1; 0 = none (pass_b self-resets)
__device__ int   g_hist[N_REL];    // relation histogram (scan kernel resets to 0 after use)
__device__ int   g_off[N_REL];     // bucket cursors (rebuilt by scan each invocation)
__device__ int4  g_sorted[NNZ];    // (s, r, o, n) sorted by relation (fully rewritten)

// ---------------------------------------------------------------------------
// Sort stage 1: smem-aggregated relation histogram. ALSO computes g_win_b
// (last-wins winner per relation) here, on the UNSORTED stream: atomics are
// spread across all 500 addresses concurrently, unlike in sorted pass_a where
// they would all hit one address at a time and serialize at the LTS atomic
// ALU (the R5 failure: 500K serialized atomicMax = ~320us).
// ---------------------------------------------------------------------------
__global__ void __launch_bounds__(256) hist_kernel(const int* __restrict__ coo) {
    __shared__ int sh_cnt[N_REL];
    __shared__ int sh_win[N_REL];
    for (int i = threadIdx.x; i < N_REL; i += blockDim.x) { sh_cnt[i] = 0; sh_win[i] = 0; }
    __syncthreads();
    int stride = gridDim.x * blockDim.x;
    for (int n = blockIdx.x * blockDim.x + threadIdx.x; n < NNZ; n += stride) {
        int r = __ldg(coo + 3 * n + 1);
        atomicAdd(&sh_cnt[r], 1);
        atomicMax(&sh_win[r], n + 1);
    }
    __syncthreads();
    for (int i = threadIdx.x; i < N_REL; i += blockDim.x) {
        if (sh_cnt[i]) {
            atomicAdd(&g_hist[i], sh_cnt[i]);
            atomicMax(&g_win_b[i], sh_win[i]);
        }
    }
}

// ---------------------------------------------------------------------------
// Sort stage 2: exclusive scan of 500 bucket counts (single block), then
// self-reset g_hist to 0 for the next invocation.
// ---------------------------------------------------------------------------
__global__ void scan_kernel() {
    __shared__ int sh[512];
    int i = threadIdx.x;
    sh[i] = (i < N_REL) ? g_hist[i] : 0;
    __syncthreads();
    for (int d = 1; d < 512; d <<= 1) {
        int v = (i >= d) ? sh[i - d] : 0;
        __syncthreads();
        sh[i] += v;
        __syncthreads();
    }
    if (i < N_REL) {
        g_off[i]  = (i == 0) ? 0 : sh[i - 1];
        g_hist[i] = 0;                       // self-reset for next invocation
    }
}

// ---------------------------------------------------------------------------
// Sort stage 3: BLOCK-AGGREGATED scatter. ~123 blocks x <=500 reservation
// atomics (never the R3 per-item contended-atomic pattern). Each block ranks
// its TILE items in smem, reserves one global range per non-empty bucket,
// then writes (s,r,o,n) tuples.
// ---------------------------------------------------------------------------
__global__ void __launch_bounds__(256) scatter_kernel(const int* __restrict__ coo) {
    __shared__ int sh_cnt[N_REL];
    __shared__ int sh_base[N_REL];

    for (int i = threadIdx.x; i < N_REL; i += blockDim.x) sh_cnt[i] = 0;
    __syncthreads();

    int base_n = blockIdx.x * TILE;
    int rr[ITEMS], lr[ITEMS];

    #pragma unroll
    for (int it = 0; it < ITEMS; it++) {
        int n = base_n + threadIdx.x + it * 256;
        if (n < NNZ) {
            int r = __ldg(coo + 3 * n + 1);
            rr[it] = r;
            lr[it] = atomicAdd(&sh_cnt[r], 1);   // local rank within (block, bucket)
        }
    }
    __syncthreads();

    for (int r = threadIdx.x; r < N_REL; r += blockDim.x) {
        int c = sh_cnt[r];
        sh_base[r] = c ? atomicAdd(&g_off[r], c) : 0;  // one global atomic per bucket
    }
    __syncthreads();

    #pragma unroll
    for (int it = 0; it < ITEMS; it++) {
        int n = base_n + threadIdx.x + it * 256;
        if (n < NNZ) {
            int s = __ldg(coo + 3 * n + 0);
            int o = __ldg(coo + 3 * n + 2);
            g_sorted[sh_base[rr[it]] + lr[it]] = make_int4(s, rr[it], o, n);
        }
    }
}

// ---------------------------------------------------------------------------
// Pass A: one warp per SORTED nnz. Consecutive warps share the same b row ->
// b gathers become L1 hits and drop out of LTS traffic. a gathers use L2-only
// loads so they don't evict b from L1. Only the g_win_a atomics remain here
// (200K distinct addresses -> spread, cheap); g_win_b was computed in
// hist_kernel on the unsorted stream.
// ---------------------------------------------------------------------------
__global__ void __launch_bounds__(256) pass_a_kernel(
    const float* __restrict__ vals,
    const float* __restrict__ a,
    const float* __restrict__ b,
    float*       __restrict__ loss)
{
    int warp = (blockIdx.x * blockDim.x + threadIdx.x) >> 5;
    int lane = threadIdx.x & 31;
    if (warp >= NNZ) return;

    int4 t = g_sorted[warp];   // same address across the warp -> broadcast
    int s = t.x, r = t.y, o = t.z, n = t.w;

    const float4* a0 = (const float4*)(a + (size_t)s * RANK);
    const float4* b1 = (const float4*)(b + (size_t)r * RANK);
    const float4* a2 = (const float4*)(a + (size_t)o * RANK);

    float sum = 0.0f;
    #pragma unroll
    for (int it = 0; it < 2; it++) {
        int j = lane + it * 32;
        if (j < RV4) {
            float4 x = __ldcg(a0 + j);   // a: L2-only (no L1 reuse; keep L1 for b)
            float4 z = __ldcg(a2 + j);
            float4 y = __ldg (b1 + j);   // b: L1-cached, shared across warps
            sum += x.x * y.x * z.x;
            sum += x.y * y.y * z.y;
            sum += x.z * y.z * z.z;
            sum += x.w * y.w * z.w;
        }
    }
    #pragma unroll
    for (int off = 16; off; off >>= 1)
        sum += __shfl_down_sync(0xffffffffu, sum, off);

    if (lane == 0) {
        float diff = sum - __ldg(vals + n);
        __stcs(loss + n, diff * diff);          // streaming: never re-read
        g_deriv[n] = 2.0f * diff;
        atomicMax(&g_win_a[s], n + 1);          // subj class
        atomicMax(&g_win_a[o], n + 1 + NNZ);    // obj class (beats subj)
    }
}

// ---------------------------------------------------------------------------
// Pass B (fused): warps [0, N_ENT) -> grad_a rows, warps [N_ENT, N_ENT+N_REL)
// -> grad_b rows. Loser rows get zeros (doubles as output init). Winner rows
// re-gather the two needed embedding rows and write d * x * y with streaming
// stores. Each warp resets its winner slot to 0 for the next invocation.
// ---------------------------------------------------------------------------
__global__ void __launch_bounds__(256) pass_b_kernel(
    const int*   __restrict__ coo,
    const float* __restrict__ a,
    const float* __restrict__ b,
    float*       __restrict__ grad_a,
    float*       __restrict__ grad_b)
{
    int warp = (blockIdx.x * blockDim.x + threadIdx.x) >> 5;
    int lane = threadIdx.x & 31;
    if (warp >= N_ENT + N_REL) return;

    float4* out;
    const float4* x;
    const float4* y;
    float d = 0.0f;
    bool have = false;

    if (warp < N_ENT) {
        out = (float4*)(grad_a + (size_t)warp * RANK);
        int k = g_win_a[warp];
        if (k > 0) {
            if (lane == 0) g_win_a[warp] = 0;        // self-reset
            bool is_obj = (k > NNZ);
            int  n      = is_obj ? (k - 1 - NNZ) : (k - 1);
            int s = coo[3 * n + 0];
            int r = coo[3 * n + 1];
            int o = coo[3 * n + 2];
            d = g_deriv[n];
            if (is_obj) {        // g_c = d * a0 * b1
                x = (const float4*)(a + (size_t)s * RANK);
                y = (const float4*)(b + (size_t)r * RANK);
            } else {             // g_a = d * b1 * a2
                x = (const float4*)(b + (size_t)r * RANK);
                y = (const float4*)(a + (size_t)o * RANK);
            }
            have = true;
        }
    } else {
        int row = warp - N_ENT;
        out = (float4*)(grad_b + (size_t)row * RANK);
        int k = g_win_b[row];
        if (k > 0) {
            if (lane == 0) g_win_b[row] = 0;         // self-reset
            int n = k - 1;
            int s = coo[3 * n + 0];
            int o = coo[3 * n + 2];
            d = g_deriv[n];
            x = (const float4*)(a + (size_t)s * RANK);   // g_b = d * a0 * a2
            y = (const float4*)(a + (size_t)o * RANK);
            have = true;
        }
    }

    if (!have) {
        float4 z = make_float4(0.f, 0.f, 0.f, 0.f);
        #pragma unroll
        for (int it = 0; it < 2; it++) {
            int j = lane + it * 32;
            if (j < RV4) __stcs(out + j, z);
        }
        return;
    }

    #pragma unroll
    for (int it = 0; it < 2; it++) {
        int j = lane + it * 32;
        if (j < RV4) {
            float4 u = __ldcg(x + j);
            float4 v = __ldcg(y + j);
            float4 w = make_float4(d * u.x * v.x, d * u.y * v.y,
                                   d * u.z * v.z, d * u.w * v.w);
            __stcs(out + j, w);
        }
    }
}

// ---------------------------------------------------------------------------
// Launch. Inputs (metadata order): coo_ns int32 [NNZ,3], vals_ns f32 [NNZ],
// a f32 [N_ENT,RANK], b f32 [N_REL,RANK].
// Output: loss[NNZ] | grad_a[N_ENT*RANK] | grad_b[N_REL*RANK]  (f32).
// ---------------------------------------------------------------------------
extern "C" void kernel_launch(void* const* d_in, const int* in_sizes, int n_in,
                              void* d_out, int out_size)
{
    const int*   coo  = (const int*)d_in[0];
    const float* vals = (const float*)d_in[1];
    const float* a    = (const float*)d_in[2];
    const float* b    = (const float*)d_in[3];

    float* out    = (float*)d_out;
    float* loss   = out;
    float* grad_a = out + NNZ;
    float* grad_b = out + NNZ + (size_t)N_ENT * RANK;

    hist_kernel<<<296, 256>>>(coo);
    scan_kernel<<<1, 512>>>();
    scatter_kernel<<<(NNZ + TILE - 1) / TILE, 256>>>(coo);

    {   // one warp per sorted nnz
        long long threads = (long long)NNZ * 32;
        int blocks = (int)((threads + 255) / 256);
        pass_a_kernel<<<blocks, 256>>>(vals, a, b, loss);
    }
    {   // one warp per output row (entity rows then relation rows)
        long long threads = (long long)(N_ENT + N_REL) * 32;
        int blocks = (int)((threads + 255) / 256);
        pass_b_kernel<<<blocks, 256>>>(coo, a, b, grad_a, grad_b);
    }
}

// round 7
// speedup vs baseline: 2.0640x; 1.1050x over previous
#include <cuda_runtime.h>
#include <cstdint>

#define RANK  200
#define NNZ   500000
#define N_ENT 200000
#define N_REL 500
#define RV4   (RANK / 4)   // 50 float4 per row

// Scratch (__device__ globals: zero-initialized at module load; pass_b
// self-resets winner slots to 0 after consuming them so every invocation —
// correctness run and each graph replay — starts identically).
__device__ float g_deriv[NNZ];     // 2 * (kruskal - val) per nnz
__device__ int   g_win_a[N_ENT];   // winner key: n+1 (subj) or n+1+NNZ (obj); 0 = none
__device__ int   g_win_b[N_REL];   // winner key: n+1; 0 = none

// ---------------------------------------------------------------------------
// Pass A: one warp per TWO nnz (independent load->fma chains double the
// memory-level parallelism per warp; R6 profiling showed pass_a is latency-
// bound: no pipe or memory level above 50%). Rank-200 dot via warp reduction;
// winner scatter-overwrite raced with atomicMax. Key encoding reproduces XLA
// sequential-scatter semantics: obj writes (.set applied second) beat subj
// writes (key n+1+NNZ vs n+1); within a class, higher nnz index wins.
// ---------------------------------------------------------------------------
__global__ void __launch_bounds__(256) pass_a_kernel(
    const int*   __restrict__ coo,
    const float* __restrict__ vals,
    const float* __restrict__ a,
    const float* __restrict__ b,
    float*       __restrict__ loss)
{
    int warp = (blockIdx.x * blockDim.x + threadIdx.x) >> 5;
    int lane = threadIdx.x & 31;
    int n0 = 2 * warp;
    int n1 = 2 * warp + 1;
    if (n0 >= NNZ) return;
    bool have1 = (n1 < NNZ);

    int s0 = __ldg(coo + 3 * n0 + 0);
    int r0 = __ldg(coo + 3 * n0 + 1);
    int o0 = __ldg(coo + 3 * n0 + 2);
    int s1 = have1 ? __ldg(coo + 3 * n1 + 0) : 0;
    int r1 = have1 ? __ldg(coo + 3 * n1 + 1) : 0;
    int o1 = have1 ? __ldg(coo + 3 * n1 + 2) : 0;

    const float4* a00 = (const float4*)(a + (size_t)s0 * RANK);
    const float4* b10 = (const float4*)(b + (size_t)r0 * RANK);
    const float4* a20 = (const float4*)(a + (size_t)o0 * RANK);
    const float4* a01 = (const float4*)(a + (size_t)s1 * RANK);
    const float4* b11 = (const float4*)(b + (size_t)r1 * RANK);
    const float4* a21 = (const float4*)(a + (size_t)o1 * RANK);

    float sum0 = 0.0f, sum1 = 0.0f;
    #pragma unroll
    for (int it = 0; it < 2; it++) {
        int j = lane + it * 32;
        if (j < RV4) {
            float4 x0 = __ldcg(a00 + j);
            float4 z0 = __ldcg(a20 + j);
            float4 y0 = __ldg (b10 + j);
            sum0 += x0.x * y0.x * z0.x;
            sum0 += x0.y * y0.y * z0.y;
            sum0 += x0.z * y0.z * z0.z;
            sum0 += x0.w * y0.w * z0.w;
            if (have1) {
                float4 x1 = __ldcg(a01 + j);
                float4 z1 = __ldcg(a21 + j);
                float4 y1 = __ldg (b11 + j);
                sum1 += x1.x * y1.x * z1.x;
                sum1 += x1.y * y1.y * z1.y;
                sum1 += x1.z * y1.z * z1.z;
                sum1 += x1.w * y1.w * z1.w;
            }
        }
    }
    #pragma unroll
    for (int off = 16; off; off >>= 1) {
        sum0 += __shfl_down_sync(0xffffffffu, sum0, off);
        sum1 += __shfl_down_sync(0xffffffffu, sum1, off);
    }

    if (lane == 0) {
        float diff0 = sum0 - __ldg(vals + n0);
        __stcs(loss + n0, diff0 * diff0);
        g_deriv[n0] = 2.0f * diff0;
        atomicMax(&g_win_a[s0], n0 + 1);
        atomicMax(&g_win_a[o0], n0 + 1 + NNZ);
        atomicMax(&g_win_b[r0], n0 + 1);
        if (have1) {
            float diff1 = sum1 - __ldg(vals + n1);
            __stcs(loss + n1, diff1 * diff1);
            g_deriv[n1] = 2.0f * diff1;
            atomicMax(&g_win_a[s1], n1 + 1);
            atomicMax(&g_win_a[o1], n1 + 1 + NNZ);
            atomicMax(&g_win_b[r1], n1 + 1);
        }
    }
}

// ---------------------------------------------------------------------------
// Pass B (fused): warps [0, N_ENT) -> grad_a rows, warps [N_ENT, N_ENT+N_REL)
// -> grad_b rows. Loser rows get zeros (doubles as output init). Winner rows
// re-gather the two needed embedding rows and write d * x * y with streaming
// stores. Each warp resets its winner slot to 0 for the next invocation.
// ---------------------------------------------------------------------------
__global__ void __launch_bounds__(256) pass_b_kernel(
    const int*   __restrict__ coo,
    const float* __restrict__ a,
    const float* __restrict__ b,
    float*       __restrict__ grad_a,
    float*       __restrict__ grad_b)
{
    int warp = (blockIdx.x * blockDim.x + threadIdx.x) >> 5;
    int lane = threadIdx.x & 31;
    if (warp >= N_ENT + N_REL) return;

    float4* out;
    const float4* x;
    const float4* y;
    float d = 0.0f;
    bool have = false;

    if (warp < N_ENT) {
        out = (float4*)(grad_a + (size_t)warp * RANK);
        int k = g_win_a[warp];
        if (k > 0) {
            if (lane == 0) g_win_a[warp] = 0;        // self-reset
            bool is_obj = (k > NNZ);
            int  n      = is_obj ? (k - 1 - NNZ) : (k - 1);
            int s = __ldg(coo + 3 * n + 0);
            int r = __ldg(coo + 3 * n + 1);
            int o = __ldg(coo + 3 * n + 2);
            d = g_deriv[n];
            if (is_obj) {        // g_c = d * a0 * b1
                x = (const float4*)(a + (size_t)s * RANK);
                y = (const float4*)(b + (size_t)r * RANK);
            } else {             // g_a = d * b1 * a2
                x = (const float4*)(b + (size_t)r * RANK);
                y = (const float4*)(a + (size_t)o * RANK);
            }
            have = true;
        }
    } else {
        int row = warp - N_ENT;
        out = (float4*)(grad_b + (size_t)row * RANK);
        int k = g_win_b[row];
        if (k > 0) {
            if (lane == 0) g_win_b[row] = 0;         // self-reset
            int n = k - 1;
            int s = __ldg(coo + 3 * n + 0);
            int o = __ldg(coo + 3 * n + 2);
            d = g_deriv[n];
            x = (const float4*)(a + (size_t)s * RANK);   // g_b = d * a0 * a2
            y = (const float4*)(a + (size_t)o * RANK);
            have = true;
        }
    }

    if (!have) {
        float4 z = make_float4(0.f, 0.f, 0.f, 0.f);
        #pragma unroll
        for (int it = 0; it < 2; it++) {
            int j = lane + it * 32;
            if (j < RV4) __stcs(out + j, z);
        }
        return;
    }

    #pragma unroll
    for (int it = 0; it < 2; it++) {
        int j = lane + it * 32;
        if (j < RV4) {
            float4 u = __ldcg(x + j);
            float4 v = __ldcg(y + j);
            float4 w = make_float4(d * u.x * v.x, d * u.y * v.y,
                                   d * u.z * v.z, d * u.w * v.w);
            __stcs(out + j, w);
        }
    }
}

// ---------------------------------------------------------------------------
// Launch. Inputs (metadata order): coo_ns int32 [NNZ,3], vals_ns f32 [NNZ],
// a f32 [N_ENT,RANK], b f32 [N_REL,RANK].
// Output: loss[NNZ] | grad_a[N_ENT*RANK] | grad_b[N_REL*RANK]  (f32).
// ---------------------------------------------------------------------------
extern "C" void kernel_launch(void* const* d_in, const int* in_sizes, int n_in,
                              void* d_out, int out_size)
{
    const int*   coo  = (const int*)d_in[0];
    const float* vals = (const float*)d_in[1];
    const float* a    = (const float*)d_in[2];
    const float* b    = (const float*)d_in[3];

    float* out    = (float*)d_out;
    float* loss   = out;
    float* grad_a = out + NNZ;
    float* grad_b = out + NNZ + (size_t)N_ENT * RANK;

    {   // one warp per two nnz
        long long warps = (NNZ + 1) / 2;
        long long threads = warps * 32;
        int blocks = (int)((threads + 255) / 256);
        pass_a_kernel<<<blocks, 256>>>(coo, vals, a, b, loss);
    }
    {   // one warp per output row (entity rows then relation rows)
        long long threads = (long long)(N_ENT + N_REL) * 32;
        int blocks = (int)((threads + 255) / 256);
        pass_b_kernel<<<blocks, 256>>>(coo, a, b, grad_a, grad_b);
    }
}

// round 8
// speedup vs baseline: 2.1236x; 1.0288x over previous
#include <cuda_runtime.h>
#include <cstdint>

#define RANK  200
#define NNZ   500000
#define N_ENT 200000
#define N_REL 500
#define RV4   (RANK / 4)   // 50 float4 per row

// Scratch (__device__ globals: zero-initialized at module load; pass_b
// self-resets winner slots to 0 after consuming them so every invocation —
// correctness run and each graph replay — starts identically).
__device__ float g_deriv[NNZ];     // 2 * (kruskal - val) per nnz
__device__ int   g_win_a[N_ENT];   // winner key: n+1 (subj) or n+1+NNZ (obj); 0 = none
__device__ int   g_win_b[N_REL];   // winner key: n+1; 0 = none

// ---------------------------------------------------------------------------
// Pass A: one warp per nnz. The 3 winner atomics are fire-and-forget RED.MAX
// and independent of the dot product, so they are issued by lanes 0/1/2 at
// the TOP of the kernel, overlapping the gather instead of serializing the
// lane-0 epilogue. vals[n] is prefetched for the same reason. launch_bounds
// (256,8) caps regs at 32 -> 64-warp occupancy ceiling (was 48 at 38 regs;
// R6 profile showed latency-bound: no unit above 55%).
// Key encoding reproduces XLA sequential-scatter semantics: obj writes (.set
// applied second) beat subj writes (key n+1+NNZ vs n+1); within a class,
// higher nnz index wins (last update wins).
// ---------------------------------------------------------------------------
__global__ void __launch_bounds__(256, 8) pass_a_kernel(
    const int*   __restrict__ coo,
    const float* __restrict__ vals,
    const float* __restrict__ a,
    const float* __restrict__ b,
    float*       __restrict__ loss)
{
    int warp = (blockIdx.x * blockDim.x + threadIdx.x) >> 5;
    int lane = threadIdx.x & 31;
    if (warp >= NNZ) return;

    int s = __ldg(coo + 3 * warp + 0);
    int r = __ldg(coo + 3 * warp + 1);
    int o = __ldg(coo + 3 * warp + 2);

    // Independent of the dot: issue immediately, spread across lanes.
    if (lane == 0) atomicMax(&g_win_a[s], warp + 1);        // subj class
    if (lane == 1) atomicMax(&g_win_a[o], warp + 1 + NNZ);  // obj class (beats subj)
    if (lane == 2) atomicMax(&g_win_b[r], warp + 1);

    float val = __ldg(vals + warp);   // prefetch (broadcast load)

    const float4* a0 = (const float4*)(a + (size_t)s * RANK);
    const float4* b1 = (const float4*)(b + (size_t)r * RANK);
    const float4* a2 = (const float4*)(a + (size_t)o * RANK);

    float sum = 0.0f;
    #pragma unroll
    for (int it = 0; it < 2; it++) {
        int j = lane + it * 32;
        if (j < RV4) {
            float4 x = __ldcg(a0 + j);   // a: L2-only (no L1 reuse; keep L1 for b)
            float4 z = __ldcg(a2 + j);
            float4 y = __ldg (b1 + j);   // b: L1-cached
            sum += x.x * y.x * z.x;
            sum += x.y * y.y * z.y;
            sum += x.z * y.z * z.z;
            sum += x.w * y.w * z.w;
        }
    }
    #pragma unroll
    for (int off = 16; off; off >>= 1)
        sum += __shfl_down_sync(0xffffffffu, sum, off);

    if (lane == 0) {
        float diff = sum - val;
        __stcs(loss + warp, diff * diff);   // streaming: never re-read
        g_deriv[warp] = 2.0f * diff;
    }
}

// ---------------------------------------------------------------------------
// Pass B (fused): warps [0, N_ENT) -> grad_a rows, warps [N_ENT, N_ENT+N_REL)
// -> grad_b rows. Loser rows get zeros (doubles as output init). Winner rows
// re-gather the two needed embedding rows and write d * x * y with streaming
// stores. Each warp resets its winner slot to 0 for the next invocation.
// ---------------------------------------------------------------------------
__global__ void __launch_bounds__(256) pass_b_kernel(
    const int*   __restrict__ coo,
    const float* __restrict__ a,
    const float* __restrict__ b,
    float*       __restrict__ grad_a,
    float*       __restrict__ grad_b)
{
    int warp = (blockIdx.x * blockDim.x + threadIdx.x) >> 5;
    int lane = threadIdx.x & 31;
    if (warp >= N_ENT + N_REL) return;

    float4* out;
    const float4* x;
    const float4* y;
    float d = 0.0f;
    bool have = false;
    bool x_is_b = false;   // b rows go through L1 (__ldg), a rows L2-only

    if (warp < N_ENT) {
        out = (float4*)(grad_a + (size_t)warp * RANK);
        int k = g_win_a[warp];
        if (k > 0) {
            if (lane == 0) g_win_a[warp] = 0;        // self-reset
            bool is_obj = (k > NNZ);
            int  n      = is_obj ? (k - 1 - NNZ) : (k - 1);
            int s = __ldg(coo + 3 * n + 0);
            int r = __ldg(coo + 3 * n + 1);
            int o = __ldg(coo + 3 * n + 2);
            d = g_deriv[n];
            if (is_obj) {        // g_c = d * a0 * b1
                x = (const float4*)(a + (size_t)s * RANK);
                y = (const float4*)(b + (size_t)r * RANK);
            } else {             // g_a = d * b1 * a2
                x = (const float4*)(b + (size_t)r * RANK); x_is_b = true;
                y = (const float4*)(a + (size_t)o * RANK);
            }
            have = true;
        }
    } else {
        int row = warp - N_ENT;
        out = (float4*)(grad_b + (size_t)row * RANK);
        int k = g_win_b[row];
        if (k > 0) {
            if (lane == 0) g_win_b[row] = 0;         // self-reset
            int n = k - 1;
            int s = __ldg(coo + 3 * n + 0);
            int o = __ldg(coo + 3 * n + 2);
            d = g_deriv[n];
            x = (const float4*)(a + (size_t)s * RANK);   // g_b = d * a0 * a2
            y = (const float4*)(a + (size_t)o * RANK);
            have = true;
        }
    }

    if (!have) {
        float4 z = make_float4(0.f, 0.f, 0.f, 0.f);
        #pragma unroll
        for (int it = 0; it < 2; it++) {
            int j = lane + it * 32;
            if (j < RV4) __stcs(out + j, z);
        }
        return;
    }

    #pragma unroll
    for (int it = 0; it < 2; it++) {
        int j = lane + it * 32;
        if (j < RV4) {
            float4 u = x_is_b ? __ldg(x + j) : __ldcg(x + j);
            float4 v = (warp < N_ENT && !x_is_b && j >= 0)
                         ? ((warp < N_ENT) ? __ldg(y + j) : __ldcg(y + j))
                         : __ldcg(y + j);
            // NOTE: for the obj-winner case y is the b row; for others y is a.
            // The ternary above keeps b rows in L1 without extra state.
            float4 w = make_float4(d * u.x * v.x, d * u.y * v.y,
                                   d * u.z * v.z, d * u.w * v.w);
            __stcs(out + j, w);
        }
    }
}

// ---------------------------------------------------------------------------
// Launch. Inputs (metadata order): coo_ns int32 [NNZ,3], vals_ns f32 [NNZ],
// a f32 [N_ENT,RANK], b f32 [N_REL,RANK].
// Output: loss[NNZ] | grad_a[N_ENT*RANK] | grad_b[N_REL*RANK]  (f32).
// ---------------------------------------------------------------------------
extern "C" void kernel_launch(void* const* d_in, const int* in_sizes, int n_in,
                              void* d_out, int out_size)
{
    const int*   coo  = (const int*)d_in[0];
    const float* vals = (const float*)d_in[1];
    const float* a    = (const float*)d_in[2];
    const float* b    = (const float*)d_in[3];

    float* out    = (float*)d_out;
    float* loss   = out;
    float* grad_a = out + NNZ;
    float* grad_b = out + NNZ + (size_t)N_ENT * RANK;

    {   // one warp per nnz
        long long threads = (long long)NNZ * 32;
        int blocks = (int)((threads + 255) / 256);
        pass_a_kernel<<<blocks, 256>>>(coo, vals, a, b, loss);
    }
    {   // one warp per output row (entity rows then relation rows)
        long long threads = (long long)(N_ENT + N_REL) * 32;
        int blocks = (int)((threads + 255) / 256);
        pass_b_kernel<<<blocks, 256>>>(coo, a, b, grad_a, grad_b);
    }
}